// round 13
// baseline (speedup 1.0000x reference)
#include <cuda_runtime.h>
#include <cstdint>

#define H      128
#define STEPS  65536
#define NC     8          // cluster = whole grid (portable size, proven)

__device__ __forceinline__ float tanh_fast(float x) {
    float y; asm("tanh.approx.f32 %0, %1;" : "=f"(y) : "f"(x)); return y;
}
__device__ __forceinline__ float sig_fast(float x) {
    return 0.5f * tanh_fast(0.5f * x) + 0.5f;
}
__device__ __forceinline__ float dot4(float4 a, float4 b) {
    return a.x * b.x + a.y * b.y + a.z * b.z + a.w * b.w;
}
__device__ __forceinline__ uint32_t smem_u32(const void* p) {
    uint32_t a;
    asm("{ .reg .u64 t; cvta.to.shared.u64 t, %1; cvt.u32.u64 %0, t; }"
        : "=r"(a) : "l"(p));
    return a;
}
__device__ __forceinline__ uint32_t mapa_u32(uint32_t a, uint32_t rank) {
    uint32_t r;
    asm("mapa.shared::cluster.u32 %0, %1, %2;" : "=r"(r) : "r"(a), "r"(rank));
    return r;
}
__device__ __forceinline__ void st_cluster_f32(uint32_t addr, float v) {
    asm volatile("st.shared::cluster.b32 [%0], %1;"
                 :: "r"(addr), "r"(__float_as_uint(v)) : "memory");
}
__device__ __forceinline__ void cluster_sync() {
    asm volatile("barrier.cluster.arrive.aligned;" ::: "memory");
    asm volatile("barrier.cluster.wait.aligned;"   ::: "memory");
}
#define CP_ASYNC16(dst, src) \
    asm volatile("cp.async.cg.shared.global [%0], [%1], 16;" \
                 :: "r"(dst), "l"(src) : "memory")
#define CP_COMMIT()  asm volatile("cp.async.commit_group;" ::: "memory")
#define CP_WAIT0()   asm volatile("cp.async.wait_group 0;" ::: "memory")

// butterfly: ALL lanes end with the full sums
template <int N>
__device__ __forceinline__ void warp_bflyN(float* s) {
#pragma unroll
    for (int off = 16; off > 0; off >>= 1)
#pragma unroll
        for (int k = 0; k < N; ++k)
            s[k] += __shfl_xor_sync(0xFFFFFFFFu, s[k], off);
}

// Dynamic smem (floats): buf0[512] | buf1[512] | wl1[64 rows * 400]
#define OFF_BUF0  0
#define OFF_BUF1  512
#define OFF_WL1   1024
#define SMEM_FLOATS (1024 + 64 * 400)

extern __shared__ float sm[];

__global__ void __launch_bounds__(512, 1) __cluster_dims__(NC, 1, 1)
fused_rnn(const float* __restrict__ inputs,
          const float* __restrict__ W_ih,
          const float* __restrict__ b_ih,
          const float* __restrict__ b_hh,
          const float* __restrict__ W_fc,
          const float* __restrict__ b_fc,
          const float* __restrict__ W_l1,
          const float* __restrict__ b_l1,
          const float* __restrict__ W_l2,
          const float* __restrict__ b_l2,
          float* __restrict__ out)
{
    const int t    = threadIdx.x;
    const int wid  = t >> 5;
    const int lane = t & 31;
    uint32_t rank;
    asm("mov.u32 %0, %%cluster_ctarank;" : "=r"(rank));
    const int G  = (int)rank * 16 + wid;     // global warp id, 0..127
    const int fc = lane & 7;                 // fan-out target CTA
    const int fk = lane >> 3;                // fan-out row slot (0..3)

    float* buf0 = sm + OFF_BUF0;
    float* buf1 = sm + OFF_BUF1;
    float* wl1s = sm + OFF_WL1;

    // ---------- x0: last-timestep input ----------
    if (t < 32)
        reinterpret_cast<float4*>(buf1)[t] =
            reinterpret_cast<const float4*>(inputs + (size_t)(STEPS - 1) * H)[t];

    // ---------- LSTM weights (regs): warp G owns the i, g, o rows of h[G] ----------
    // PyTorch gate order i,f,g,o -> rows G, 256+G, 384+G (f dead: c0=0).
    float4 wl[3][3]; float bl[3][3];
#pragma unroll
    for (int l = 0; l < 3; ++l) {
        const int rows[3] = { G, 256 + G, 384 + G };
#pragma unroll
        for (int k = 0; k < 3; ++k) {
            wl[l][k] = reinterpret_cast<const float4*>(
                           W_ih + ((size_t)l * 512 + rows[k]) * H)[lane];
            bl[l][k] = b_ih[l * 512 + rows[k]] + b_hh[l * 512 + rows[k]];
        }
    }

    // ---------- FC weights (regs): rows G + 128k, k<4 (r<400) ----------
    float4 wfc[4]; float bfc[4];
#pragma unroll
    for (int k = 0; k < 4; ++k) {
        const int r = G + 128 * k;
        if (r < 400) {
            wfc[k] = reinterpret_cast<const float4*>(W_fc + (size_t)r * H)[lane];
            bfc[k] = b_fc[r];
        }
    }

    // ---------- L2 weights (regs): row G < 63 ----------
    float4 w2[4]; float b2 = 0.0f;
    if (G < 63) {
        const float4* wr = reinterpret_cast<const float4*>(W_l2 + (size_t)G * 500);
        w2[0] = wr[lane]; w2[1] = wr[lane + 32]; w2[2] = wr[lane + 64];
        if (lane < 29) w2[3] = wr[lane + 96];
        b2 = b_l2[G];
    }

    // ---------- L1 weights (cp.async -> smem): rows G + 128k, k<4 (r<500) ----------
    float bl1[4];
#pragma unroll
    for (int k = 0; k < 4; ++k) {
        const int r = G + 128 * k;
        if (r < 500) {
            const float* src = W_l1 + (size_t)r * 400;
            uint32_t dst = smem_u32(wl1s + (wid * 4 + k) * 400);
            CP_ASYNC16(dst + 16 * lane,        src + 4 * lane);
            CP_ASYNC16(dst + 16 * (lane + 32), src + 4 * (lane + 32));
            CP_ASYNC16(dst + 16 * (lane + 64), src + 4 * (lane + 64));
            if (lane < 4)
                CP_ASYNC16(dst + 16 * (lane + 96), src + 4 * (lane + 96));
            bl1[k] = b_l1[r];
        }
    }
    CP_COMMIT();

    __syncthreads();   // x0 visible CTA-wide

    // ================= LSTM layers: warp G produces finished h[G] =================
    // l=0: buf1 -> buf0; l=1: buf0 -> buf1; l=2: buf1 -> buf0
#pragma unroll
    for (int l = 0; l < 3; ++l) {
        float* xb = (l == 1) ? buf0 : buf1;
        float* hb = (l == 1) ? buf1 : buf0;

        const float4 x = reinterpret_cast<const float4*>(xb)[lane];
        float s[3];
#pragma unroll
        for (int k = 0; k < 3; ++k) s[k] = dot4(wl[l][k], x);
        warp_bflyN<3>(s);                      // all lanes: i,g,o sums

        const float c = sig_fast(s[0] + bl[l][0]) * tanh_fast(s[1] + bl[l][1]);
        const float h = sig_fast(s[2] + bl[l][2]) * tanh_fast(c);
        if (lane < 8)                           // fan finished h to all CTAs
            st_cluster_f32(mapa_u32(smem_u32(&hb[G]), lane), h);

        cluster_sync();                         // release stores / acquire reads
    }

    // ================= FC 400x128: buf0 -> buf1 =================
    {
        const float4 x = reinterpret_cast<const float4*>(buf0)[lane];
        float s[4];
#pragma unroll
        for (int k = 0; k < 4; ++k)
            s[k] = (G + 128 * k < 400) ? dot4(wfc[k], x) : 0.0f;
        warp_bflyN<4>(s);

        const int r = G + 128 * fk;             // 32 lanes = 4 rows x 8 CTAs
        if (r < 400) {
            float v = s[0] + bfc[0];
#pragma unroll
            for (int k = 1; k < 4; ++k)
                if (fk == k) v = s[k] + bfc[k];
            st_cluster_f32(mapa_u32(smem_u32(&buf1[r]), fc), v);
        }
        cluster_sync();
    }

    // ================= L1 500x400: buf1 -> buf0 =================
    {
        CP_WAIT0();
        __syncthreads();                        // all lanes' cp.async rows done

        const float4* xf = reinterpret_cast<const float4*>(buf1);
        const float4 x0 = xf[lane], x1 = xf[lane + 32], x2 = xf[lane + 64];
        float4 x3 = make_float4(0.f, 0.f, 0.f, 0.f);
        if (lane < 4) x3 = xf[lane + 96];

        float s[4];
#pragma unroll
        for (int k = 0; k < 4; ++k) {
            float v = 0.0f;
            if (G + 128 * k < 500) {
                const float4* wr = reinterpret_cast<const float4*>(
                    wl1s + (wid * 4 + k) * 400);
                v = dot4(wr[lane], x0) + dot4(wr[lane + 32], x1)
                  + dot4(wr[lane + 64], x2);
                if (lane < 4) v += dot4(wr[lane + 96], x3);
            }
            s[k] = v;
        }
        warp_bflyN<4>(s);

        const int r = G + 128 * fk;
        if (r < 500) {
            float v = s[0] + bl1[0];
#pragma unroll
            for (int k = 1; k < 4; ++k)
                if (fk == k) v = s[k] + bl1[k];
            st_cluster_f32(mapa_u32(smem_u32(&buf0[r]), fc), v);
        }
        cluster_sync();
    }

    // ================= L2 63x500: buf0 -> gmem =================
    if (G < 63) {
        const float4* xf = reinterpret_cast<const float4*>(buf0);
        float s[1];
        s[0] = dot4(w2[0], xf[lane]) + dot4(w2[1], xf[lane + 32])
             + dot4(w2[2], xf[lane + 64]);
        if (lane < 29) s[0] += dot4(w2[3], xf[lane + 96]);
        warp_bflyN<1>(s);
        if (lane == 0) out[G] = s[0] + b2;
    }
}

extern "C" void kernel_launch(void* const* d_in, const int* in_sizes, int n_in,
                              void* d_out, int out_size) {
    const float* inputs = (const float*)d_in[0];
    const float* W_ih   = (const float*)d_in[1];
    // d_in[2] = W_hh — dead (h0 = 0)
    const float* b_ih   = (const float*)d_in[3];
    const float* b_hh   = (const float*)d_in[4];
    const float* W_fc   = (const float*)d_in[5];
    const float* b_fc   = (const float*)d_in[6];
    const float* W_l1   = (const float*)d_in[7];
    const float* b_l1   = (const float*)d_in[8];
    const float* W_l2   = (const float*)d_in[9];
    const float* b_l2   = (const float*)d_in[10];
    float* out = (float*)d_out;

    const int dynSmem = SMEM_FLOATS * 4;     // ~106 KB
    cudaFuncSetAttribute(fused_rnn,
                         cudaFuncAttributeMaxDynamicSharedMemorySize, dynSmem);

    fused_rnn<<<NC, 512, dynSmem>>>(inputs, W_ih, b_ih, b_hh,
                                    W_fc, b_fc, W_l1, b_l1, W_l2, b_l2, out);
}

// round 14
// speedup vs baseline: 1.0853x; 1.0853x over previous
#include <cuda_runtime.h>
#include <cstdint>

#define H      128
#define STEPS  65536
#define NC     8          // cluster = whole grid (portable size, proven)

__device__ __forceinline__ float tanh_fast(float x) {
    float y; asm("tanh.approx.f32 %0, %1;" : "=f"(y) : "f"(x)); return y;
}
__device__ __forceinline__ float sig_fast(float x) {
    return 0.5f * tanh_fast(0.5f * x) + 0.5f;
}
__device__ __forceinline__ float dot4(float4 a, float4 b) {
    return a.x * b.x + a.y * b.y + a.z * b.z + a.w * b.w;
}
__device__ __forceinline__ uint32_t smem_u32(const void* p) {
    uint32_t a;
    asm("{ .reg .u64 t; cvta.to.shared.u64 t, %1; cvt.u32.u64 %0, t; }"
        : "=r"(a) : "l"(p));
    return a;
}
__device__ __forceinline__ uint32_t mapa_u32(uint32_t a, uint32_t rank) {
    uint32_t r;
    asm("mapa.shared::cluster.u32 %0, %1, %2;" : "=r"(r) : "r"(a), "r"(rank));
    return r;
}
__device__ __forceinline__ void st_cluster_f32(uint32_t addr, float v) {
    asm volatile("st.shared::cluster.b32 [%0], %1;"
                 :: "r"(addr), "r"(__float_as_uint(v)) : "memory");
}
__device__ __forceinline__ void cluster_sync() {
    asm volatile("barrier.cluster.arrive.aligned;" ::: "memory");
    asm volatile("barrier.cluster.wait.aligned;"   ::: "memory");
}
__device__ __forceinline__ void mbar_init(uint32_t mb, uint32_t cnt) {
    asm volatile("mbarrier.init.shared.b64 [%0], %1;" :: "r"(mb), "r"(cnt) : "memory");
}
__device__ __forceinline__ void mbar_inval(uint32_t mb) {
    asm volatile("mbarrier.inval.shared.b64 [%0];" :: "r"(mb) : "memory");
}
__device__ __forceinline__ void mbar_expect_tx(uint32_t mb, uint32_t bytes) {
    asm volatile("mbarrier.arrive.expect_tx.shared.b64 _, [%0], %1;"
                 :: "r"(mb), "r"(bytes) : "memory");
}
// 1D bulk copy gmem -> local smem, completion -> mbar (no tensormap needed)
__device__ __forceinline__ void tma_bulk_1d(uint32_t dst, const void* src,
                                            uint32_t bytes, uint32_t mb) {
    asm volatile(
        "cp.async.bulk.shared::cluster.global.mbarrier::complete_tx::bytes "
        "[%0], [%1], %2, [%3];"
        :: "r"(dst), "l"(src), "r"(bytes), "r"(mb) : "memory");
}
__device__ __forceinline__ void mbar_wait0(uint32_t mb) {
    uint32_t done;
    asm volatile(
        "{\n\t.reg .pred p;\n\t"
        "mbarrier.try_wait.parity.acquire.cta.shared::cta.b64 p, [%1], 0;\n\t"
        "selp.b32 %0, 1, 0, p;\n\t}"
        : "=r"(done) : "r"(mb) : "memory");
    if (!done) {
        asm volatile(
            "{\n\t.reg .pred P1;\n"
            "W%=:\n\t"
            "mbarrier.try_wait.parity.acquire.cta.shared::cta.b64 P1, [%0], 0, 0x989680;\n\t"
            "@P1 bra D%=;\n\t"
            "bra W%=;\n"
            "D%=:\n\t}"
            :: "r"(mb) : "memory");
    }
}

// butterfly: ALL lanes end with the full sums
template <int N>
__device__ __forceinline__ void warp_bflyN(float* s) {
#pragma unroll
    for (int off = 16; off > 0; off >>= 1)
#pragma unroll
        for (int k = 0; k < N; ++k)
            s[k] += __shfl_xor_sync(0xFFFFFFFFu, s[k], off);
}

// Dynamic smem (floats): buf0[512] | buf1[512] | wl1[63 rows * 400]
#define OFF_BUF0  0
#define OFF_BUF1  512
#define OFF_WL1   1024
#define SMEM_FLOATS (1024 + 63 * 400)

extern __shared__ float sm[];

__global__ void __launch_bounds__(512, 1) __cluster_dims__(NC, 1, 1)
fused_rnn(const float* __restrict__ inputs,
          const float* __restrict__ W_ih,
          const float* __restrict__ b_ih,
          const float* __restrict__ b_hh,
          const float* __restrict__ W_fc,
          const float* __restrict__ b_fc,
          const float* __restrict__ W_l1,
          const float* __restrict__ b_l1,
          const float* __restrict__ W_l2,
          const float* __restrict__ b_l2,
          float* __restrict__ out)
{
    __shared__ __align__(8) unsigned long long tma_mbar;

    const int t    = threadIdx.x;
    const int wid  = t >> 5;
    const int lane = t & 31;
    uint32_t rank;
    asm("mov.u32 %0, %%cluster_ctarank;" : "=r"(rank));
    const int G  = (int)rank * 16 + wid;     // global warp id, 0..127
    const int fc = lane & 7;                 // fan-out target CTA
    const int fk = lane >> 3;                // fan-out row slot (0..3)

    float* buf0 = sm + OFF_BUF0;
    float* buf1 = sm + OFF_BUF1;
    float* wl1s = sm + OFF_WL1;

    const uint32_t mb = smem_u32(&tma_mbar);
    if (t == 0) mbar_init(mb, 1);

    // ---------- x0: last-timestep input ----------
    if (t < 32)
        reinterpret_cast<float4*>(buf1)[t] =
            reinterpret_cast<const float4*>(inputs + (size_t)(STEPS - 1) * H)[t];

    // ---------- LSTM weights (regs): warp G owns the i, g, o rows of h[G] ----------
    // PyTorch gate order i,f,g,o -> rows G, 256+G, 384+G (f dead: c0=0).
    float4 wl[3][3]; float bl[3][3];
#pragma unroll
    for (int l = 0; l < 3; ++l) {
        const int rows[3] = { G, 256 + G, 384 + G };
#pragma unroll
        for (int k = 0; k < 3; ++k) {
            wl[l][k] = reinterpret_cast<const float4*>(
                           W_ih + ((size_t)l * 512 + rows[k]) * H)[lane];
            bl[l][k] = b_ih[l * 512 + rows[k]] + b_hh[l * 512 + rows[k]];
        }
    }

    // ---------- FC weights (regs): rows G + 128k, k<4 (r<400) ----------
    float4 wfc[4]; float bfc[4];
#pragma unroll
    for (int k = 0; k < 4; ++k) {
        const int r = G + 128 * k;
        if (r < 400) {
            wfc[k] = reinterpret_cast<const float4*>(W_fc + (size_t)r * H)[lane];
            bfc[k] = b_fc[r];
        }
    }

    // ---------- L2 weights (regs): row G < 63 ----------
    float4 w2[4]; float b2 = 0.0f;
    if (G < 63) {
        const float4* wr = reinterpret_cast<const float4*>(W_l2 + (size_t)G * 500);
        w2[0] = wr[lane]; w2[1] = wr[lane + 32]; w2[2] = wr[lane + 64];
        if (lane < 29) w2[3] = wr[lane + 96];
        b2 = b_l2[G];
    }

    // ---------- L1: contiguous row block per CTA, fetched by ONE TMA bulk ----------
    // CTA rank owns rows [rank*63, rank*63 + nrows), nrows = 63 (rank 7: 59).
    const int nrows = (rank == 7) ? 59 : 63;
    float bl1[4];
#pragma unroll
    for (int k = 0; k < 4; ++k) {
        const int l = wid + 16 * k;
        if (l < nrows) bl1[k] = b_l1[rank * 63 + l];
    }

    __syncthreads();   // x0 + mbar init visible CTA-wide

    if (t == 0) {      // issue the bulk copy (TMA engine; off the LSU path)
        const uint32_t bytes = (uint32_t)nrows * 400u * 4u;
        mbar_expect_tx(mb, bytes);
        tma_bulk_1d(smem_u32(wl1s), W_l1 + (size_t)rank * 63 * 400, bytes, mb);
    }

    // ================= LSTM layers: warp G produces finished h[G] =================
    // l=0: buf1 -> buf0; l=1: buf0 -> buf1; l=2: buf1 -> buf0
#pragma unroll
    for (int l = 0; l < 3; ++l) {
        float* xb = (l == 1) ? buf0 : buf1;
        float* hb = (l == 1) ? buf1 : buf0;

        const float4 x = reinterpret_cast<const float4*>(xb)[lane];
        float s[3];
#pragma unroll
        for (int k = 0; k < 3; ++k) s[k] = dot4(wl[l][k], x);
        warp_bflyN<3>(s);                      // all lanes: i,g,o sums

        const float c = sig_fast(s[0] + bl[l][0]) * tanh_fast(s[1] + bl[l][1]);
        const float h = sig_fast(s[2] + bl[l][2]) * tanh_fast(c);
        if (lane < 8)                           // fan finished h to all CTAs
            st_cluster_f32(mapa_u32(smem_u32(&hb[G]), lane), h);

        cluster_sync();                         // release stores / acquire reads
    }

    // ================= FC 400x128: buf0 -> buf1 =================
    {
        const float4 x = reinterpret_cast<const float4*>(buf0)[lane];
        float s[4];
#pragma unroll
        for (int k = 0; k < 4; ++k)
            s[k] = (G + 128 * k < 400) ? dot4(wfc[k], x) : 0.0f;
        warp_bflyN<4>(s);

        const int r = G + 128 * fk;             // 32 lanes = 4 rows x 8 CTAs
        if (r < 400) {
            float v = s[0] + bfc[0];
#pragma unroll
            for (int k = 1; k < 4; ++k)
                if (fk == k) v = s[k] + bfc[k];
            st_cluster_f32(mapa_u32(smem_u32(&buf1[r]), fc), v);
        }
        cluster_sync();
    }

    // ================= L1 500x400: buf1 -> buf0 (weights via TMA) =================
    {
        mbar_wait0(mb);                         // TMA complete + acquire

        const float4* xf = reinterpret_cast<const float4*>(buf1);
        const float4 x0 = xf[lane], x1 = xf[lane + 32], x2 = xf[lane + 64];
        float4 x3 = make_float4(0.f, 0.f, 0.f, 0.f);
        if (lane < 4) x3 = xf[lane + 96];

        float s[4];
#pragma unroll
        for (int k = 0; k < 4; ++k) {
            float v = 0.0f;
            const int l = wid + 16 * k;
            if (l < nrows) {
                const float4* wr = reinterpret_cast<const float4*>(wl1s + l * 400);
                v = dot4(wr[lane], x0) + dot4(wr[lane + 32], x1)
                  + dot4(wr[lane + 64], x2);
                if (lane < 4) v += dot4(wr[lane + 96], x3);
            }
            s[k] = v;
        }
        warp_bflyN<4>(s);

        const int l = wid + 16 * fk;            // 32 lanes = 4 rows x 8 CTAs
        if (l < nrows) {
            float v = s[0] + bl1[0];
#pragma unroll
            for (int k = 1; k < 4; ++k)
                if (fk == k) v = s[k] + bl1[k];
            st_cluster_f32(mapa_u32(smem_u32(&buf0[rank * 63 + l]), fc), v);
        }
        cluster_sync();
    }

    // ================= L2 63x500: buf0 -> gmem =================
    if (G < 63) {
        const float4* xf = reinterpret_cast<const float4*>(buf0);
        float s[1];
        s[0] = dot4(w2[0], xf[lane]) + dot4(w2[1], xf[lane + 32])
             + dot4(w2[2], xf[lane + 64]);
        if (lane < 29) s[0] += dot4(w2[3], xf[lane + 96]);
        warp_bflyN<1>(s);
        if (lane == 0) out[G] = s[0] + b2;
    }

    // hygiene for graph replays: inval so next launch's init is clean.
    __syncthreads();
    if (t == 0) mbar_inval(mb);
}

extern "C" void kernel_launch(void* const* d_in, const int* in_sizes, int n_in,
                              void* d_out, int out_size) {
    const float* inputs = (const float*)d_in[0];
    const float* W_ih   = (const float*)d_in[1];
    // d_in[2] = W_hh — dead (h0 = 0)
    const float* b_ih   = (const float*)d_in[3];
    const float* b_hh   = (const float*)d_in[4];
    const float* W_fc   = (const float*)d_in[5];
    const float* b_fc   = (const float*)d_in[6];
    const float* W_l1   = (const float*)d_in[7];
    const float* b_l1   = (const float*)d_in[8];
    const float* W_l2   = (const float*)d_in[9];
    const float* b_l2   = (const float*)d_in[10];
    float* out = (float*)d_out;

    const int dynSmem = SMEM_FLOATS * 4;     // ~103 KB
    cudaFuncSetAttribute(fused_rnn,
                         cudaFuncAttributeMaxDynamicSharedMemorySize, dynSmem);

    fused_rnn<<<NC, 512, dynSmem>>>(inputs, W_ih, b_ih, b_hh,
                                    W_fc, b_fc, W_l1, b_l1, W_l2, b_l2, out);
}